// round 1
// baseline (speedup 1.0000x reference)
#include <cuda_runtime.h>
#include <math.h>

#define BN    8
#define CINC  256
#define CMID  128
#define COUTC 256
#define HH    128
#define WW    128

// ---------------- scratch (static __device__ — allocation-free) ----------------
// g_wp[0..3]: branch weights repacked [ci][k=kh*3+kw][co(128)], scale-folded
// g_wp[4]  : w2 repacked            [ci][k][co(256)], scale-folded
__device__ float g_wp[5][294912];
__device__ float g_wp1[65536];                 // w1 repacked [ci][co(256)], scale-folded
__device__ float g_y[4][BN * CMID * HH * WW];  // branch conv outputs (post-relu)
__device__ float g_S[BN * CMID * HH * WW];     // sum of 4 scanned branches

// ---------------- weight repack (+BN scale fold) ----------------
__global__ void k_repack3(const float* __restrict__ w, const float* __restrict__ s, int which)
{
    int idx = blockIdx.x * 256 + threadIdx.x;
    if (idx >= 294912) return;
    int cin  = (which < 4) ? CINC : CMID;
    int cout = (which < 4) ? CMID : COUTC;
    int co   = idx % cout;
    int rest = idx / cout;
    int k    = rest % 9;
    int ci   = rest / 9;
    g_wp[which][idx] = w[(co * cin + ci) * 9 + k] * s[co];
}

__global__ void k_repack1(const float* __restrict__ w, const float* __restrict__ s)
{
    int idx = blockIdx.x * 256 + threadIdx.x;
    if (idx >= 65536) return;
    int co = idx & 255;
    int ci = idx >> 8;
    g_wp1[idx] = w[co * 256 + ci] * s[co];
}

// ---------------- fused 4-branch 3x3 conv + BN + relu ----------------
// One block: all 128 out-channels x one full output row (128 px) of one branch.
// grid = (H=128, B=8, branch=4), 256 threads, 8co x 8px per thread.
__global__ __launch_bounds__(256, 2) void k_conv_branch(
    const float* __restrict__ x,
    const float* __restrict__ ob0, const float* __restrict__ ob1,
    const float* __restrict__ ob2, const float* __restrict__ ob3)
{
    const int h   = blockIdx.x;
    const int b   = blockIdx.y;
    const int br  = blockIdx.z;
    const int tid = threadIdx.x;
    const int tx  = tid & 15;   // pixel group: px = tx + 16*j
    const int ty  = tid >> 4;   // co group:    co = ty*8 + i

    __shared__ float xs[4][3][130];   // 4 ci x 3 rows x (128 + 2 pad)
    __shared__ float ws[4][9][128];   // 4 ci x 9 taps x 128 co

    const float* __restrict__ wp = g_wp[br];

    float acc[8][8];
#pragma unroll
    for (int i = 0; i < 8; i++)
#pragma unroll
        for (int j = 0; j < 8; j++) acc[i][j] = 0.f;

    for (int cb = 0; cb < CINC; cb += 4) {
        __syncthreads();
        {   // weights: layout matches global exactly -> coalesced copy
            float* wl = &ws[0][0][0];
            const float* src = wp + cb * (9 * CMID);
#pragma unroll
            for (int i = 0; i < 18; i++) wl[tid + 256 * i] = src[tid + 256 * i];
        }
        for (int i = tid; i < 4 * 3 * 130; i += 256) {
            int ci  = i / 390;
            int rem = i - ci * 390;
            int r   = rem / 130;
            int c   = rem - r * 130;
            int hh  = h + r - 1;
            int wq  = c - 1;
            float v = 0.f;
            if ((unsigned)hh < (unsigned)HH && (unsigned)wq < (unsigned)WW)
                v = x[((b * CINC + cb + ci) * HH + hh) * WW + wq];
            xs[ci][r][c] = v;
        }
        __syncthreads();
#pragma unroll 1
        for (int ci = 0; ci < 4; ci++) {
#pragma unroll
            for (int kh = 0; kh < 3; kh++) {
#pragma unroll
                for (int kw = 0; kw < 3; kw++) {
                    float wv[8], xv[8];
#pragma unroll
                    for (int i = 0; i < 8; i++) wv[i] = ws[ci][kh * 3 + kw][ty * 8 + i];
#pragma unroll
                    for (int j = 0; j < 8; j++) xv[j] = xs[ci][kh][tx + 16 * j + kw];
#pragma unroll
                    for (int i = 0; i < 8; i++)
#pragma unroll
                        for (int j = 0; j < 8; j++)
                            acc[i][j] = fmaf(wv[i], xv[j], acc[i][j]);
                }
            }
        }
    }

    const float* ob = (br == 0) ? ob0 : (br == 1) ? ob1 : (br == 2) ? ob2 : ob3;
    float* yb = g_y[br];
#pragma unroll
    for (int i = 0; i < 8; i++) {
        int co = ty * 8 + i;
        float sh = ob[co];
        float* row = yb + ((b * CMID + co) * HH + h) * WW;
#pragma unroll
        for (int j = 0; j < 8; j++) {
            float v = acc[i][j] + sh;
            row[tx + 16 * j] = v > 0.f ? v : 0.f;
        }
    }
}

// ---------------- scans along W: S = revcummax_w(yl) + cummax_w(yr) ----------------
__global__ void k_scan_w()
{
    int bc = blockIdx.x;          // b*128 + c
    int h  = threadIdx.x;         // 0..127
    const float* yl = g_y[0] + bc * (HH * WW) + h * WW;
    const float* yr = g_y[1] + bc * (HH * WW) + h * WW;
    float* Sp = g_S + bc * (HH * WW) + h * WW;
    float m = -INFINITY;
    for (int w = WW - 1; w >= 0; --w) { m = fmaxf(m, yl[w]); Sp[w] = m; }
    m = -INFINITY;
    for (int w = 0; w < WW; ++w)    { m = fmaxf(m, yr[w]); Sp[w] += m; }
}

// ---------------- scans along H: S += revcummax_h(yt) + cummax_h(yb) ----------------
__global__ void k_scan_h()
{
    int bc = blockIdx.x;
    int w  = threadIdx.x;         // 0..127 (coalesced)
    const float* yt = g_y[2] + bc * (HH * WW) + w;
    const float* yv = g_y[3] + bc * (HH * WW) + w;
    float* Sp = g_S + bc * (HH * WW) + w;
    float m = -INFINITY;
    for (int hq = HH - 1; hq >= 0; --hq) { m = fmaxf(m, yt[hq * WW]); Sp[hq * WW] += m; }
    m = -INFINITY;
    for (int hq = 0; hq < HH; ++hq)      { m = fmaxf(m, yv[hq * WW]); Sp[hq * WW] += m; }
}

// ---------------- conv2 3x3 over S + 1x1 skip over x + relu -> out ----------------
// grid = (H=128, B=8, cotile=2), 256 threads, tile = 128co x 128px.
__global__ __launch_bounds__(256, 2) void k_conv_out(
    const float* __restrict__ x,
    const float* __restrict__ o2v, const float* __restrict__ o1v,
    float* __restrict__ out)
{
    const int h   = blockIdx.x;
    const int b   = blockIdx.y;
    const int ct  = blockIdx.z;  // 0..1 (co tile of 128)
    const int tid = threadIdx.x;
    const int tx  = tid & 15;
    const int ty  = tid >> 4;

    __shared__ float xs[4][3][130];
    __shared__ float ws[4][9][128];
    __shared__ float xs1[16][128];
    __shared__ float ws1[16][128];

    float acc[8][8];
#pragma unroll
    for (int i = 0; i < 8; i++)
#pragma unroll
        for (int j = 0; j < 8; j++) acc[i][j] = 0.f;

    // ---- Part A: 3x3 conv over g_S (128 input channels) ----
    for (int cb = 0; cb < CMID; cb += 4) {
        __syncthreads();
        {
            float* wl = &ws[0][0][0];
#pragma unroll
            for (int ii = 0; ii < 18; ii++) {
                int i    = tid + 256 * ii;        // [ci][k][co128] linear
                int co   = i & 127;
                int rest = i >> 7;
                int k    = rest % 9;
                int ci   = rest / 9;
                wl[i] = g_wp[4][((cb + ci) * 9 + k) * COUTC + ct * 128 + co];
            }
        }
        for (int i = tid; i < 4 * 3 * 130; i += 256) {
            int ci  = i / 390;
            int rem = i - ci * 390;
            int r   = rem / 130;
            int c   = rem - r * 130;
            int hh  = h + r - 1;
            int wq  = c - 1;
            float v = 0.f;
            if ((unsigned)hh < (unsigned)HH && (unsigned)wq < (unsigned)WW)
                v = g_S[((b * CMID + cb + ci) * HH + hh) * WW + wq];
            xs[ci][r][c] = v;
        }
        __syncthreads();
#pragma unroll 1
        for (int ci = 0; ci < 4; ci++) {
#pragma unroll
            for (int kh = 0; kh < 3; kh++) {
#pragma unroll
                for (int kw = 0; kw < 3; kw++) {
                    float wv[8], xv[8];
#pragma unroll
                    for (int i = 0; i < 8; i++) wv[i] = ws[ci][kh * 3 + kw][ty * 8 + i];
#pragma unroll
                    for (int j = 0; j < 8; j++) xv[j] = xs[ci][kh][tx + 16 * j + kw];
#pragma unroll
                    for (int i = 0; i < 8; i++)
#pragma unroll
                        for (int j = 0; j < 8; j++)
                            acc[i][j] = fmaf(wv[i], xv[j], acc[i][j]);
                }
            }
        }
    }

    // ---- Part B: 1x1 skip conv over x (256 input channels) ----
    for (int cb = 0; cb < CINC; cb += 16) {
        __syncthreads();
#pragma unroll
        for (int ii = 0; ii < 8; ii++) {
            int i  = tid + 256 * ii;              // 2048 elements each
            int ci = i >> 7;
            int wq = i & 127;
            xs1[ci][wq] = x[((b * CINC + cb + ci) * HH + h) * WW + wq];
            ws1[ci][wq] = g_wp1[(cb + ci) * COUTC + ct * 128 + wq];
        }
        __syncthreads();
#pragma unroll 1
        for (int ci = 0; ci < 16; ci++) {
            float wv[8], xv[8];
#pragma unroll
            for (int i = 0; i < 8; i++) wv[i] = ws1[ci][ty * 8 + i];
#pragma unroll
            for (int j = 0; j < 8; j++) xv[j] = xs1[ci][tx + 16 * j];
#pragma unroll
            for (int i = 0; i < 8; i++)
#pragma unroll
                for (int j = 0; j < 8; j++)
                    acc[i][j] = fmaf(wv[i], xv[j], acc[i][j]);
        }
    }

    // ---- epilogue: + (o2 + o1), relu, store ----
#pragma unroll
    for (int i = 0; i < 8; i++) {
        int co = ct * 128 + ty * 8 + i;
        float sh = o2v[co] + o1v[co];
        float* row = out + ((b * COUTC + co) * HH + h) * WW;
#pragma unroll
        for (int j = 0; j < 8; j++) {
            float v = acc[i][j] + sh;
            row[tx + 16 * j] = v > 0.f ? v : 0.f;
        }
    }
}

// ---------------- launch ----------------
extern "C" void kernel_launch(void* const* d_in, const int* in_sizes, int n_in,
                              void* d_out, int out_size)
{
    const float* x   = (const float*)d_in[0];
    const float* w_l = (const float*)d_in[1];
    const float* s_l = (const float*)d_in[2];
    const float* o_l = (const float*)d_in[3];
    const float* w_r = (const float*)d_in[4];
    const float* s_r = (const float*)d_in[5];
    const float* o_r = (const float*)d_in[6];
    const float* w_t = (const float*)d_in[7];
    const float* s_t = (const float*)d_in[8];
    const float* o_t = (const float*)d_in[9];
    const float* w_b = (const float*)d_in[10];
    const float* s_b = (const float*)d_in[11];
    const float* o_b = (const float*)d_in[12];
    const float* w2  = (const float*)d_in[13];
    const float* s2  = (const float*)d_in[14];
    const float* o2  = (const float*)d_in[15];
    const float* w1  = (const float*)d_in[16];
    const float* s1  = (const float*)d_in[17];
    const float* o1  = (const float*)d_in[18];
    float* out = (float*)d_out;

    k_repack3<<<1152, 256>>>(w_l, s_l, 0);
    k_repack3<<<1152, 256>>>(w_r, s_r, 1);
    k_repack3<<<1152, 256>>>(w_t, s_t, 2);
    k_repack3<<<1152, 256>>>(w_b, s_b, 3);
    k_repack3<<<1152, 256>>>(w2,  s2,  4);
    k_repack1<<<256, 256>>>(w1, s1);

    dim3 g1(HH, BN, 4);
    k_conv_branch<<<g1, 256>>>(x, o_l, o_r, o_t, o_b);
    k_scan_w<<<BN * CMID, 128>>>();
    k_scan_h<<<BN * CMID, 128>>>();
    dim3 g3(HH, BN, 2);
    k_conv_out<<<g3, 256>>>(x, o2, o1, out);
}

// round 2
// speedup vs baseline: 1.0019x; 1.0019x over previous
#include <cuda_runtime.h>
#include <math.h>

#define BN    8
#define CINC  256
#define CMID  128
#define COUTC 256
#define HH    128
#define WW    128

// ---------------- scratch (static __device__ — allocation-free) ----------------
// g_wp[0..3]: branch weights repacked [ci][k=kh*3+kw][co(128)], scale-folded
// g_wp[4]  : w2 repacked            [ci][k][co(256)], scale-folded
__device__ float g_wp[5][294912];
__device__ float g_wp1[65536];                 // w1 repacked [ci][co(256)], scale-folded
__device__ float g_y[4][BN * CMID * HH * WW];  // branch conv outputs (post-relu)
__device__ float g_S[BN * CMID * HH * WW];     // sum of 4 scanned branches

// ---------------- weight repack (+BN scale fold) ----------------
__global__ void k_repack3(const float* __restrict__ w, const float* __restrict__ s, int which)
{
    int idx = blockIdx.x * 256 + threadIdx.x;
    if (idx >= 294912) return;
    int cin  = (which < 4) ? CINC : CMID;
    int cout = (which < 4) ? CMID : COUTC;
    int co   = idx % cout;
    int rest = idx / cout;
    int k    = rest % 9;
    int ci   = rest / 9;
    g_wp[which][idx] = w[(co * cin + ci) * 9 + k] * s[co];
}

__global__ void k_repack1(const float* __restrict__ w, const float* __restrict__ s)
{
    int idx = blockIdx.x * 256 + threadIdx.x;
    if (idx >= 65536) return;
    int co = idx & 255;
    int ci = idx >> 8;
    g_wp1[idx] = w[co * 256 + ci] * s[co];
}

// ---------------- fused 4-branch 3x3 conv + BN + relu ----------------
// One block: all 128 out-channels x one full output row (128 px) of one branch.
// grid = (H=128, B=8, branch=4), 256 threads, 8co x 8px per thread.
__global__ __launch_bounds__(256, 2) void k_conv_branch(
    const float* __restrict__ x,
    const float* __restrict__ ob0, const float* __restrict__ ob1,
    const float* __restrict__ ob2, const float* __restrict__ ob3)
{
    const int h   = blockIdx.x;
    const int b   = blockIdx.y;
    const int br  = blockIdx.z;
    const int tid = threadIdx.x;
    const int tx  = tid & 15;   // pixel group: px = tx + 16*j
    const int ty  = tid >> 4;   // co group:    co = ty*8 + i

    __shared__ float xs[4][3][130];   // 4 ci x 3 rows x (128 + 2 pad)
    __shared__ float ws[4][9][128];   // 4 ci x 9 taps x 128 co

    const float* __restrict__ wp = g_wp[br];

    float acc[8][8];
#pragma unroll
    for (int i = 0; i < 8; i++)
#pragma unroll
        for (int j = 0; j < 8; j++) acc[i][j] = 0.f;

    for (int cb = 0; cb < CINC; cb += 4) {
        __syncthreads();
        {   // weights: layout matches global exactly -> coalesced copy
            float* wl = &ws[0][0][0];
            const float* src = wp + cb * (9 * CMID);
#pragma unroll
            for (int i = 0; i < 18; i++) wl[tid + 256 * i] = src[tid + 256 * i];
        }
        for (int i = tid; i < 4 * 3 * 130; i += 256) {
            int ci  = i / 390;
            int rem = i - ci * 390;
            int r   = rem / 130;
            int c   = rem - r * 130;
            int hh  = h + r - 1;
            int wq  = c - 1;
            float v = 0.f;
            if ((unsigned)hh < (unsigned)HH && (unsigned)wq < (unsigned)WW)
                v = x[((b * CINC + cb + ci) * HH + hh) * WW + wq];
            xs[ci][r][c] = v;
        }
        __syncthreads();
#pragma unroll 1
        for (int ci = 0; ci < 4; ci++) {
#pragma unroll
            for (int kh = 0; kh < 3; kh++) {
#pragma unroll
                for (int kw = 0; kw < 3; kw++) {
                    float wv[8], xv[8];
#pragma unroll
                    for (int i = 0; i < 8; i++) wv[i] = ws[ci][kh * 3 + kw][ty * 8 + i];
#pragma unroll
                    for (int j = 0; j < 8; j++) xv[j] = xs[ci][kh][tx + 16 * j + kw];
#pragma unroll
                    for (int i = 0; i < 8; i++)
#pragma unroll
                        for (int j = 0; j < 8; j++)
                            acc[i][j] = fmaf(wv[i], xv[j], acc[i][j]);
                }
            }
        }
    }

    const float* ob = (br == 0) ? ob0 : (br == 1) ? ob1 : (br == 2) ? ob2 : ob3;
    float* yb = g_y[br];
#pragma unroll
    for (int i = 0; i < 8; i++) {
        int co = ty * 8 + i;
        float sh = ob[co];
        float* row = yb + ((b * CMID + co) * HH + h) * WW;
#pragma unroll
        for (int j = 0; j < 8; j++) {
            float v = acc[i][j] + sh;
            row[tx + 16 * j] = v > 0.f ? v : 0.f;
        }
    }
}

// ---------------- scans along W: S = revcummax_w(yl) + cummax_w(yr) ----------------
__global__ void k_scan_w()
{
    int bc = blockIdx.x;          // b*128 + c
    int h  = threadIdx.x;         // 0..127
    const float* yl = g_y[0] + bc * (HH * WW) + h * WW;
    const float* yr = g_y[1] + bc * (HH * WW) + h * WW;
    float* Sp = g_S + bc * (HH * WW) + h * WW;
    float m = -INFINITY;
    for (int w = WW - 1; w >= 0; --w) { m = fmaxf(m, yl[w]); Sp[w] = m; }
    m = -INFINITY;
    for (int w = 0; w < WW; ++w)    { m = fmaxf(m, yr[w]); Sp[w] += m; }
}

// ---------------- scans along H: S += revcummax_h(yt) + cummax_h(yb) ----------------
__global__ void k_scan_h()
{
    int bc = blockIdx.x;
    int w  = threadIdx.x;         // 0..127 (coalesced)
    const float* yt = g_y[2] + bc * (HH * WW) + w;
    const float* yv = g_y[3] + bc * (HH * WW) + w;
    float* Sp = g_S + bc * (HH * WW) + w;
    float m = -INFINITY;
    for (int hq = HH - 1; hq >= 0; --hq) { m = fmaxf(m, yt[hq * WW]); Sp[hq * WW] += m; }
    m = -INFINITY;
    for (int hq = 0; hq < HH; ++hq)      { m = fmaxf(m, yv[hq * WW]); Sp[hq * WW] += m; }
}

// ---------------- conv2 3x3 over S + 1x1 skip over x + relu -> out ----------------
// grid = (H=128, B=8, cotile=2), 256 threads, tile = 128co x 128px.
__global__ __launch_bounds__(256, 2) void k_conv_out(
    const float* __restrict__ x,
    const float* __restrict__ o2v, const float* __restrict__ o1v,
    float* __restrict__ out)
{
    const int h   = blockIdx.x;
    const int b   = blockIdx.y;
    const int ct  = blockIdx.z;  // 0..1 (co tile of 128)
    const int tid = threadIdx.x;
    const int tx  = tid & 15;
    const int ty  = tid >> 4;

    __shared__ float xs[4][3][130];
    __shared__ float ws[4][9][128];
    __shared__ float xs1[16][128];
    __shared__ float ws1[16][128];

    float acc[8][8];
#pragma unroll
    for (int i = 0; i < 8; i++)
#pragma unroll
        for (int j = 0; j < 8; j++) acc[i][j] = 0.f;

    // ---- Part A: 3x3 conv over g_S (128 input channels) ----
    for (int cb = 0; cb < CMID; cb += 4) {
        __syncthreads();
        {
            float* wl = &ws[0][0][0];
#pragma unroll
            for (int ii = 0; ii < 18; ii++) {
                int i    = tid + 256 * ii;        // [ci][k][co128] linear
                int co   = i & 127;
                int rest = i >> 7;
                int k    = rest % 9;
                int ci   = rest / 9;
                wl[i] = g_wp[4][((cb + ci) * 9 + k) * COUTC + ct * 128 + co];
            }
        }
        for (int i = tid; i < 4 * 3 * 130; i += 256) {
            int ci  = i / 390;
            int rem = i - ci * 390;
            int r   = rem / 130;
            int c   = rem - r * 130;
            int hh  = h + r - 1;
            int wq  = c - 1;
            float v = 0.f;
            if ((unsigned)hh < (unsigned)HH && (unsigned)wq < (unsigned)WW)
                v = g_S[((b * CMID + cb + ci) * HH + hh) * WW + wq];
            xs[ci][r][c] = v;
        }
        __syncthreads();
#pragma unroll 1
        for (int ci = 0; ci < 4; ci++) {
#pragma unroll
            for (int kh = 0; kh < 3; kh++) {
#pragma unroll
                for (int kw = 0; kw < 3; kw++) {
                    float wv[8], xv[8];
#pragma unroll
                    for (int i = 0; i < 8; i++) wv[i] = ws[ci][kh * 3 + kw][ty * 8 + i];
#pragma unroll
                    for (int j = 0; j < 8; j++) xv[j] = xs[ci][kh][tx + 16 * j + kw];
#pragma unroll
                    for (int i = 0; i < 8; i++)
#pragma unroll
                        for (int j = 0; j < 8; j++)
                            acc[i][j] = fmaf(wv[i], xv[j], acc[i][j]);
                }
            }
        }
    }

    // ---- Part B: 1x1 skip conv over x (256 input channels) ----
    for (int cb = 0; cb < CINC; cb += 16) {
        __syncthreads();
#pragma unroll
        for (int ii = 0; ii < 8; ii++) {
            int i  = tid + 256 * ii;              // 2048 elements each
            int ci = i >> 7;
            int wq = i & 127;
            xs1[ci][wq] = x[((b * CINC + cb + ci) * HH + h) * WW + wq];
            ws1[ci][wq] = g_wp1[(cb + ci) * COUTC + ct * 128 + wq];
        }
        __syncthreads();
#pragma unroll 1
        for (int ci = 0; ci < 16; ci++) {
            float wv[8], xv[8];
#pragma unroll
            for (int i = 0; i < 8; i++) wv[i] = ws1[ci][ty * 8 + i];
#pragma unroll
            for (int j = 0; j < 8; j++) xv[j] = xs1[ci][tx + 16 * j];
#pragma unroll
            for (int i = 0; i < 8; i++)
#pragma unroll
                for (int j = 0; j < 8; j++)
                    acc[i][j] = fmaf(wv[i], xv[j], acc[i][j]);
        }
    }

    // ---- epilogue: + (o2 + o1), relu, store ----
#pragma unroll
    for (int i = 0; i < 8; i++) {
        int co = ct * 128 + ty * 8 + i;
        float sh = o2v[co] + o1v[co];
        float* row = out + ((b * COUTC + co) * HH + h) * WW;
#pragma unroll
        for (int j = 0; j < 8; j++) {
            float v = acc[i][j] + sh;
            row[tx + 16 * j] = v > 0.f ? v : 0.f;
        }
    }
}

// ---------------- launch ----------------
extern "C" void kernel_launch(void* const* d_in, const int* in_sizes, int n_in,
                              void* d_out, int out_size)
{
    const float* x   = (const float*)d_in[0];
    const float* w_l = (const float*)d_in[1];
    const float* s_l = (const float*)d_in[2];
    const float* o_l = (const float*)d_in[3];
    const float* w_r = (const float*)d_in[4];
    const float* s_r = (const float*)d_in[5];
    const float* o_r = (const float*)d_in[6];
    const float* w_t = (const float*)d_in[7];
    const float* s_t = (const float*)d_in[8];
    const float* o_t = (const float*)d_in[9];
    const float* w_b = (const float*)d_in[10];
    const float* s_b = (const float*)d_in[11];
    const float* o_b = (const float*)d_in[12];
    const float* w2  = (const float*)d_in[13];
    const float* s2  = (const float*)d_in[14];
    const float* o2  = (const float*)d_in[15];
    const float* w1  = (const float*)d_in[16];
    const float* s1  = (const float*)d_in[17];
    const float* o1  = (const float*)d_in[18];
    float* out = (float*)d_out;

    k_repack3<<<1152, 256>>>(w_l, s_l, 0);
    k_repack3<<<1152, 256>>>(w_r, s_r, 1);
    k_repack3<<<1152, 256>>>(w_t, s_t, 2);
    k_repack3<<<1152, 256>>>(w_b, s_b, 3);
    k_repack3<<<1152, 256>>>(w2,  s2,  4);
    k_repack1<<<256, 256>>>(w1, s1);

    dim3 g1(HH, BN, 4);
    k_conv_branch<<<g1, 256>>>(x, o_l, o_r, o_t, o_b);
    k_scan_w<<<BN * CMID, 128>>>();
    k_scan_h<<<BN * CMID, 128>>>();
    dim3 g3(HH, BN, 2);
    k_conv_out<<<g3, 256>>>(x, o2, o1, out);
}